// round 13
// baseline (speedup 1.0000x reference)
#include <cuda_runtime.h>
#include <cuda_fp16.h>
#include <cstdint>

#define BATCH 4
#define SEQ   2048
#define HEADS 16
#define DHEAD 64
#define DIMM  1024
#define MTOT  (BATCH*SEQ)

#define PAD 72
#define PAD2 40
#define LOG2E 1.4426950408889634f

// ---------------- scratch ----------------
__device__ __half g_q[BATCH*HEADS*SEQ*DHEAD];   // [B,H,N,64] (q pre-scaled by 1/8)
__device__ __half g_k[BATCH*HEADS*SEQ*DHEAD];
__device__ __half g_v[BATCH*HEADS*SEQ*DHEAD];
__device__ __half g_ao[MTOT*DIMM];              // [B,N,H*64]
__device__ __half g_xh[MTOT*DIMM];              // x in fp16
__device__ __half g_wqkvT[3*DIMM*DIMM];         // [n=3072][k=1024]
__device__ __half g_woutT[DIMM*DIMM];           // [n=1024][k=1024]

__device__ __forceinline__ float ex2f_(float x) {
    float y; asm("ex2.approx.f32 %0, %1;" : "=f"(y) : "f"(x)); return y;
}
// pack two fp32 (log2-domain) into half2, exponentiate both with ONE MUFU op
__device__ __forceinline__ unsigned ex2h2(float a, float b) {
    __half2 h = __floats2half2_rn(a, b);
    unsigned hu = *(unsigned*)&h, r;
    asm("ex2.approx.f16x2 %0, %1;" : "=r"(r) : "r"(hu));
    return r;
}
__device__ __forceinline__ unsigned s2u(const void* p) {
    return (unsigned)__cvta_generic_to_shared(p);
}
__device__ __forceinline__ void cpa16(unsigned d, const void* s) {
    asm volatile("cp.async.cg.shared.global [%0], [%1], 16;" :: "r"(d), "l"(s));
}
__device__ __forceinline__ void cpcommit() { asm volatile("cp.async.commit_group;"); }
template<int N> __device__ __forceinline__ void cpwait() {
    asm volatile("cp.async.wait_group %0;" :: "n"(N));
}
__device__ __forceinline__ void ldsm4(unsigned& r0, unsigned& r1, unsigned& r2, unsigned& r3, unsigned a) {
    asm volatile("ldmatrix.sync.aligned.m8n8.x4.shared.b16 {%0,%1,%2,%3}, [%4];"
                 : "=r"(r0), "=r"(r1), "=r"(r2), "=r"(r3) : "r"(a));
}
__device__ __forceinline__ void ldsm4t(unsigned& r0, unsigned& r1, unsigned& r2, unsigned& r3, unsigned a) {
    asm volatile("ldmatrix.sync.aligned.m8n8.x4.trans.shared.b16 {%0,%1,%2,%3}, [%4];"
                 : "=r"(r0), "=r"(r1), "=r"(r2), "=r"(r3) : "r"(a));
}
__device__ __forceinline__ void mma16816(float* c, const unsigned* a, unsigned b0, unsigned b1) {
    asm volatile(
        "mma.sync.aligned.m16n8k16.row.col.f32.f16.f16.f32 "
        "{%0,%1,%2,%3}, {%4,%5,%6,%7}, {%8,%9}, {%0,%1,%2,%3};\n"
        : "+f"(c[0]), "+f"(c[1]), "+f"(c[2]), "+f"(c[3])
        : "r"(a[0]), "r"(a[1]), "r"(a[2]), "r"(a[3]), "r"(b0), "r"(b1));
}

// ---------------- kernel 0: fused prep (x convert + both weight transposes) ----------------
// grid.x sections: [0, 4096) x_convert | [4096, 4096+3072) wqkv | [+1024) wout
#define XCONV_BLOCKS (MTOT*DIMM/(256*8))      // 4096
#define WQKV_BLOCKS  ((3*DIMM/32)*(DIMM/32))  // 96*32 = 3072
#define WOUT_BLOCKS  ((DIMM/32)*(DIMM/32))    // 1024
__global__ void prep_kernel(const float* __restrict__ X,
                            const float* __restrict__ Wqkv,
                            const float* __restrict__ Wout) {
    int blk = blockIdx.x;
    if (blk < XCONV_BLOCKS) {
        int tid = threadIdx.x;                 // 256 threads, 8 floats each
        if (tid < 256) {
            int i = blk * 256 + tid;
            const float4* Xv = (const float4*)X;
            float4 a = Xv[2*i], b = Xv[2*i + 1];
            __half2 h0 = __floats2half2_rn(a.x, a.y);
            __half2 h1 = __floats2half2_rn(a.z, a.w);
            __half2 h2 = __floats2half2_rn(b.x, b.y);
            __half2 h3 = __floats2half2_rn(b.z, b.w);
            uint4 u;
            u.x = *(unsigned*)&h0; u.y = *(unsigned*)&h1;
            u.z = *(unsigned*)&h2; u.w = *(unsigned*)&h3;
            *(uint4*)&g_xh[(size_t)i * 8] = u;
        }
        return;
    }
    __shared__ float tile[32][33];
    const float* in;
    __half* out;
    int nb, kb, Nc;
    if (blk < XCONV_BLOCKS + WQKV_BLOCKS) {
        int b2 = blk - XCONV_BLOCKS;
        in = Wqkv; out = g_wqkvT; Nc = 3*DIMM;
        nb = (b2 % (3*DIMM/32)) * 32; kb = (b2 / (3*DIMM/32)) * 32;
    } else {
        int b2 = blk - XCONV_BLOCKS - WQKV_BLOCKS;
        in = Wout; out = g_woutT; Nc = DIMM;
        nb = (b2 % (DIMM/32)) * 32; kb = (b2 / (DIMM/32)) * 32;
    }
    int tx = threadIdx.x & 31, ty = threadIdx.x >> 5;  // 32x8
    #pragma unroll
    for (int i = 0; i < 32; i += 8)
        tile[ty + i][tx] = in[(size_t)(kb + ty + i) * Nc + nb + tx];
    __syncthreads();
    #pragma unroll
    for (int i = 0; i < 32; i += 8)
        out[(size_t)(nb + ty + i) * DIMM + kb + tx] = __float2half_rn(tile[tx][ty + i]);
}

// ---------------- dense GEMM core: CTA 128x128, warp 64x32, K-chunk 32, 5 stages ----------------
#define ST_A_H   (128 * PAD2)
#define ST_H     (2 * ST_A_H)                 // 10240 halves = 20480 B
#define KITERS   (DIMM / 32)                  // 32
#define NSTAGE   5
#define GEMM2_SMEM (NSTAGE * ST_H * (int)sizeof(__half))   // 102,400 B

__device__ __forceinline__ void g2_stage(__half* sbuf, const __half* Ag, const __half* Bg,
                                         int kt, int tid) {
    __half* sA = sbuf;
    __half* sB = sbuf + ST_A_H;
    int r0 = tid >> 2, c = tid & 3;
    #pragma unroll
    for (int i = 0; i < 2; i++) {
        int r = r0 + i * 64;
        cpa16(s2u(&sA[r * PAD2 + c * 8]), &Ag[(size_t)r * DIMM + kt * 32 + c * 8]);
        cpa16(s2u(&sB[r * PAD2 + c * 8]), &Bg[(size_t)r * DIMM + kt * 32 + c * 8]);
    }
}

__device__ __forceinline__ void g2_compute(const __half* sbuf, float acc[4][4][4],
                                           int lane, int wm, int wn) {
    const __half* sA = sbuf;
    const __half* sB = sbuf + ST_A_H;
    int r8 = lane & 7;
    int b3 = (lane >> 3) & 1, b4 = (lane >> 4) & 1;
    #pragma unroll
    for (int kk = 0; kk < 2; kk++) {
        unsigned a[4][4], b[4][2];
        #pragma unroll
        for (int mt = 0; mt < 4; mt++) {
            unsigned ad = s2u(&sA[(wm*64 + mt*16 + b3*8 + r8) * PAD2 + kk*16 + b4*8]);
            ldsm4(a[mt][0], a[mt][1], a[mt][2], a[mt][3], ad);
        }
        #pragma unroll
        for (int jp = 0; jp < 2; jp++) {
            unsigned bd = s2u(&sB[(wn*32 + jp*16 + b4*8 + r8) * PAD2 + kk*16 + b3*8]);
            unsigned u0, u1, u2, u3;
            ldsm4(u0, u1, u2, u3, bd);
            b[2*jp][0] = u0;   b[2*jp][1] = u1;
            b[2*jp+1][0] = u2; b[2*jp+1][1] = u3;
        }
        #pragma unroll
        for (int mt = 0; mt < 4; mt++)
            #pragma unroll
            for (int nt = 0; nt < 4; nt++)
                mma16816(acc[mt][nt], a[mt], b[nt][0], b[nt][1]);
    }
}

__device__ __forceinline__ void g2_mainloop(__half* smem, const __half* Ag, const __half* Bg,
                                            float acc[4][4][4], int tid, int lane,
                                            int wm, int wn) {
    #pragma unroll
    for (int s = 0; s < NSTAGE - 1; s++) {
        g2_stage(smem + s * ST_H, Ag, Bg, s, tid);
        cpcommit();
    }
    int slot = 0, nslot = NSTAGE - 1;
    for (int kt = 0; kt < KITERS; kt++) {
        cpwait<NSTAGE - 2>();
        __syncthreads();
        g2_compute(smem + slot * ST_H, acc, lane, wm, wn);
        if (kt + NSTAGE - 1 < KITERS)
            g2_stage(smem + nslot * ST_H, Ag, Bg, kt + NSTAGE - 1, tid);
        cpcommit();   // exactly one commit per iter: wait bound stays exact
        if (++slot == NSTAGE) slot = 0;
        if (++nslot == NSTAGE) nslot = 0;
    }
}

// ---------------- kernel 1: QKV GEMM (128x128 tiles) ----------------
__global__ __launch_bounds__(256, 2) void qkv_gemm() {
    extern __shared__ __half smem_[];
    int bn = blockIdx.x, bm = blockIdx.y;
    int tid = threadIdx.x, lane = tid & 31, warp = tid >> 5;
    int wm = warp >> 2, wn = warp & 3;
    int g = lane >> 2, t = lane & 3;
    const __half* Ag = g_xh + (size_t)bm * 128 * DIMM;
    const __half* Bg = g_wqkvT + (size_t)bn * 128 * DIMM;

    float acc[4][4][4];
    #pragma unroll
    for (int i = 0; i < 4; i++)
        #pragma unroll
        for (int j = 0; j < 4; j++)
            #pragma unroll
            for (int k = 0; k < 4; k++) acc[i][j][k] = 0.f;

    g2_mainloop(smem_, Ag, Bg, acc, tid, lane, wm, wn);

    int sec = bn >> 3;
    __half* dst = sec == 0 ? g_q : (sec == 1 ? g_k : g_v);
    float scale = (sec == 0) ? 0.125f : 1.0f;
    #pragma unroll
    for (int mt = 0; mt < 4; mt++) {
        int r = bm*128 + wm*64 + mt*16 + g;
        int bb = r >> 11, nq = r & (SEQ - 1);
        #pragma unroll
        for (int nt = 0; nt < 4; nt++) {
            int cc = (bn & 7)*128 + wn*32 + nt*8 + 2*t;
            int h = cc >> 6, d = cc & 63;
            int o = ((bb*HEADS + h)*SEQ + nq)*DHEAD + d;
            *(__half2*)&dst[o] = __floats2half2_rn(acc[mt][nt][0]*scale, acc[mt][nt][1]*scale);
            *(__half2*)&dst[o + 8*DHEAD] = __floats2half2_rn(acc[mt][nt][2]*scale, acc[mt][nt][3]*scale);
        }
    }
}

// ---------------- kernel 3: out proj (128x128 tiles) ----------------
__global__ __launch_bounds__(256, 2) void out_gemm(const float* __restrict__ bias,
                                                   float* __restrict__ out) {
    extern __shared__ __half smem_[];
    int bn = blockIdx.x, bm = blockIdx.y;
    int tid = threadIdx.x, lane = tid & 31, warp = tid >> 5;
    int wm = warp >> 2, wn = warp & 3;
    int g = lane >> 2, t = lane & 3;
    const __half* Ag = g_ao + (size_t)bm * 128 * DIMM;
    const __half* Bg = g_woutT + (size_t)bn * 128 * DIMM;

    float acc[4][4][4];
    #pragma unroll
    for (int i = 0; i < 4; i++)
        #pragma unroll
        for (int j = 0; j < 4; j++)
            #pragma unroll
            for (int k = 0; k < 4; k++) acc[i][j][k] = 0.f;

    g2_mainloop(smem_, Ag, Bg, acc, tid, lane, wm, wn);

    #pragma unroll
    for (int mt = 0; mt < 4; mt++) {
        int r = bm*128 + wm*64 + mt*16 + g;
        #pragma unroll
        for (int nt = 0; nt < 4; nt++) {
            int c = bn*128 + wn*32 + nt*8 + 2*t;
            float2 bv = *(const float2*)&bias[c];
            float2 r0; r0.x = acc[mt][nt][0] + bv.x; r0.y = acc[mt][nt][1] + bv.y;
            float2 r1; r1.x = acc[mt][nt][2] + bv.x; r1.y = acc[mt][nt][3] + bv.y;
            *(float2*)&out[(size_t)r*DIMM + c] = r0;
            *(float2*)&out[(size_t)(r + 8)*DIMM + c] = r1;
        }
    }
}

// ---------------- kernel 2: flash attention, 4-deep KV ring, f16x2 softmax (R12 winner) ----------------
#define KV_H (64 * PAD)                       // halves per K (or V) tile
#define ATTN_SMEM ((128 * PAD + 8 * KV_H) * (int)sizeof(__half))
#define KVTILES (SEQ / 64)                    // 32

__device__ __forceinline__ void attn_stage_kv(__half* sK, __half* sV,
                                              const __half* Kg, const __half* Vg,
                                              int kv, int tid) {
    const __half* Kn = Kg + (size_t)kv * 64 * DHEAD;
    const __half* Vn = Vg + (size_t)kv * 64 * DHEAD;
    int r0 = tid >> 3, c = tid & 7;
    #pragma unroll
    for (int i = 0; i < 2; i++) {
        int r = r0 + i * 32;
        cpa16(s2u(&sK[r * PAD + c * 8]), &Kn[r * DHEAD + c * 8]);
        cpa16(s2u(&sV[r * PAD + c * 8]), &Vn[r * DHEAD + c * 8]);
    }
}

__global__ __launch_bounds__(256, 2) void attn_kernel() {
    extern __shared__ __half smem_[];
    __half* sQ  = smem_;                       // 128*PAD
    __half* sKr = smem_ + 128 * PAD;           // ring: 4 x KV_H
    __half* sVr = sKr + 4 * KV_H;              // ring: 4 x KV_H
    int rt = blockIdx.x, pair = blockIdx.y;
    int tid = threadIdx.x, lane = tid & 31, warp = tid >> 5;
    int g = lane >> 2, t = lane & 3;
    int r8 = lane & 7;
    int b3 = (lane >> 3) & 1, b4 = (lane >> 4) & 1;
    const __half* Qg = g_q + (size_t)pair * SEQ * DHEAD + (size_t)rt * 128 * DHEAD;
    const __half* Kg = g_k + (size_t)pair * SEQ * DHEAD;
    const __half* Vg = g_v + (size_t)pair * SEQ * DHEAD;

    // group 1: Q
    {
        int r0 = tid >> 3, c = tid & 7;
        #pragma unroll
        for (int i = 0; i < 4; i++) {
            int r = r0 + i * 32;
            cpa16(s2u(&sQ[r * PAD + c * 8]), &Qg[r * DHEAD + c * 8]);
        }
    }
    cpcommit();
    // groups 2..4: kv tiles 0..2
    attn_stage_kv(sKr + 0 * KV_H, sVr + 0 * KV_H, Kg, Vg, 0, tid); cpcommit();
    attn_stage_kv(sKr + 1 * KV_H, sVr + 1 * KV_H, Kg, Vg, 1, tid); cpcommit();
    attn_stage_kv(sKr + 2 * KV_H, sVr + 2 * KV_H, Kg, Vg, 2, tid); cpcommit();

    cpwait<3>();   // Q landed
    __syncthreads();
    unsigned qa[4][4];
    #pragma unroll
    for (int kk = 0; kk < 4; kk++) {
        unsigned ad = s2u(&sQ[(warp*16 + b3*8 + r8) * PAD + kk*16 + b4*8]);
        ldsm4(qa[kk][0], qa[kk][1], qa[kk][2], qa[kk][3], ad);
    }

    float m0 = -1e30f, m1 = -1e30f, l0 = 0.f, l1 = 0.f;
    float o[8][4];
    #pragma unroll
    for (int nd = 0; nd < 8; nd++)
        #pragma unroll
        for (int i = 0; i < 4; i++) o[nd][i] = 0.f;

    for (int kv = 0; kv < KVTILES; kv++) {
        // commits before this iter = 4 + kv; wait<2> -> completed >= kv+2 -> tile kv landed
        cpwait<2>();
        __syncthreads();
        // stage tile kv+3 into ring slot (kv+3)&3 = (kv-1)&3 (freed by the sync above)
        if (kv + 3 < KVTILES)
            attn_stage_kv(sKr + ((kv + 3) & 3) * KV_H, sVr + ((kv + 3) & 3) * KV_H,
                          Kg, Vg, kv + 3, tid);
        cpcommit();   // exactly one commit per iter
        const __half* cK = sKr + (kv & 3) * KV_H;
        const __half* cV = sVr + (kv & 3) * KV_H;

        float s[8][4];
        #pragma unroll
        for (int jn = 0; jn < 8; jn++)
            #pragma unroll
            for (int i = 0; i < 4; i++) s[jn][i] = 0.f;
        #pragma unroll
        for (int kk = 0; kk < 4; kk++)
            #pragma unroll
            for (int jp = 0; jp < 4; jp++) {
                unsigned bd = s2u(&cK[(jp*16 + b4*8 + r8) * PAD + kk*16 + b3*8]);
                unsigned u0, u1, u2, u3;
                ldsm4(u0, u1, u2, u3, bd);
                mma16816(s[2*jp],   qa[kk], u0, u1);
                mma16816(s[2*jp+1], qa[kk], u2, u3);
            }
        // online softmax (rows g = sum0, g+8 = sum1)
        float rmax0 = -1e30f, rmax1 = -1e30f;
        #pragma unroll
        for (int jn = 0; jn < 8; jn++) {
            rmax0 = fmaxf(rmax0, fmaxf(s[jn][0], s[jn][1]));
            rmax1 = fmaxf(rmax1, fmaxf(s[jn][2], s[jn][3]));
        }
        rmax0 = fmaxf(rmax0, __shfl_xor_sync(0xffffffffu, rmax0, 1));
        rmax0 = fmaxf(rmax0, __shfl_xor_sync(0xffffffffu, rmax0, 2));
        rmax1 = fmaxf(rmax1, __shfl_xor_sync(0xffffffffu, rmax1, 1));
        rmax1 = fmaxf(rmax1, __shfl_xor_sync(0xffffffffu, rmax1, 2));
        float mn0 = fmaxf(m0, rmax0), mn1 = fmaxf(m1, rmax1);
        float al0 = ex2f_((m0 - mn0) * LOG2E);
        float al1 = ex2f_((m1 - mn1) * LOG2E);
        float c0 = mn0 * LOG2E, c1 = mn1 * LOG2E;

        // P directly in fp16 A-fragment layout via f16x2 exp; sums from same fp16 P
        unsigned pa[4][4];
        float sum0 = 0.f, sum1 = 0.f;
        #pragma unroll
        for (int kk = 0; kk < 4; kk++) {
            pa[kk][0] = ex2h2(s[2*kk][0]  *LOG2E - c0, s[2*kk][1]  *LOG2E - c0);
            pa[kk][1] = ex2h2(s[2*kk][2]  *LOG2E - c1, s[2*kk][3]  *LOG2E - c1);
            pa[kk][2] = ex2h2(s[2*kk+1][0]*LOG2E - c0, s[2*kk+1][1]*LOG2E - c0);
            pa[kk][3] = ex2h2(s[2*kk+1][2]*LOG2E - c1, s[2*kk+1][3]*LOG2E - c1);
            __half2 e0 = __hadd2(*(__half2*)&pa[kk][0], *(__half2*)&pa[kk][2]);
            __half2 e1 = __hadd2(*(__half2*)&pa[kk][1], *(__half2*)&pa[kk][3]);
            float2 f0 = __half22float2(e0);
            float2 f1 = __half22float2(e1);
            sum0 += f0.x + f0.y;
            sum1 += f1.x + f1.y;
        }
        sum0 += __shfl_xor_sync(0xffffffffu, sum0, 1);
        sum0 += __shfl_xor_sync(0xffffffffu, sum0, 2);
        sum1 += __shfl_xor_sync(0xffffffffu, sum1, 1);
        sum1 += __shfl_xor_sync(0xffffffffu, sum1, 2);
        l0 = l0 * al0 + sum0;  l1 = l1 * al1 + sum1;
        m0 = mn0;  m1 = mn1;
        #pragma unroll
        for (int nd = 0; nd < 8; nd++) {
            o[nd][0] *= al0; o[nd][1] *= al0; o[nd][2] *= al1; o[nd][3] *= al1;
        }
        #pragma unroll
        for (int kk = 0; kk < 4; kk++)
            #pragma unroll
            for (int np = 0; np < 4; np++) {
                unsigned vd = s2u(&cV[(kk*16 + b3*8 + r8) * PAD + np*16 + b4*8]);
                unsigned u0, u1, u2, u3;
                ldsm4t(u0, u1, u2, u3, vd);
                mma16816(o[2*np],   pa[kk], u0, u1);
                mma16816(o[2*np+1], pa[kk], u2, u3);
            }
    }
    float inv0 = 1.0f / l0, inv1 = 1.0f / l1;
    int bb = pair >> 4, h = pair & 15;
    int r = rt*128 + warp*16 + g;
    size_t base0 = ((size_t)bb*SEQ + r)*DIMM + h*64;
    #pragma unroll
    for (int nd = 0; nd < 8; nd++) {
        int d = nd*8 + 2*t;
        *(__half2*)&g_ao[base0 + d] = __floats2half2_rn(o[nd][0]*inv0, o[nd][1]*inv0);
        *(__half2*)&g_ao[base0 + (size_t)8*DIMM + d] = __floats2half2_rn(o[nd][2]*inv1, o[nd][3]*inv1);
    }
}

// ---------------- launch ----------------
extern "C" void kernel_launch(void* const* d_in, const int* in_sizes, int n_in,
                              void* d_out, int out_size) {
    const float* x     = (const float*)d_in[0];
    const float* w_qkv = (const float*)d_in[1];
    const float* w_out = (const float*)d_in[2];
    const float* b_out = (const float*)d_in[3];
    float* out = (float*)d_out;

    cudaFuncSetAttribute(qkv_gemm, cudaFuncAttributeMaxDynamicSharedMemorySize, GEMM2_SMEM);
    cudaFuncSetAttribute(out_gemm, cudaFuncAttributeMaxDynamicSharedMemorySize, GEMM2_SMEM);
    cudaFuncSetAttribute(attn_kernel, cudaFuncAttributeMaxDynamicSharedMemorySize, ATTN_SMEM);

    prep_kernel<<<XCONV_BLOCKS + WQKV_BLOCKS + WOUT_BLOCKS, 256>>>(x, w_qkv, w_out);
    qkv_gemm<<<dim3(3*DIMM/128, MTOT/128), 256, GEMM2_SMEM>>>();
    attn_kernel<<<dim3(SEQ/128, BATCH*HEADS), 256, ATTN_SMEM>>>();
    out_gemm<<<dim3(DIMM/128, MTOT/128), 256, GEMM2_SMEM>>>(b_out, out);
}

// round 14
// speedup vs baseline: 1.0346x; 1.0346x over previous
#include <cuda_runtime.h>
#include <cuda_fp16.h>
#include <cstdint>

#define BATCH 4
#define SEQ   2048
#define HEADS 16
#define DHEAD 64
#define DIMM  1024
#define MTOT  (BATCH*SEQ)

#define PAD 72
#define PAD2 40
#define LOG2E 1.4426950408889634f

// ---------------- scratch ----------------
__device__ __half g_q[BATCH*HEADS*SEQ*DHEAD];   // [B,H,N,64] (q pre-scaled by 1/8)
__device__ __half g_k[BATCH*HEADS*SEQ*DHEAD];
__device__ __half g_v[BATCH*HEADS*SEQ*DHEAD];
__device__ __half g_ao[MTOT*DIMM];              // [B,N,H*64]
__device__ __half g_xh[MTOT*DIMM];              // x in fp16
__device__ __half g_wqkvT[3*DIMM*DIMM];         // [n=3072][k=1024]
__device__ __half g_woutT[DIMM*DIMM];           // [n=1024][k=1024]

__device__ __forceinline__ float ex2f_(float x) {
    float y; asm("ex2.approx.f32 %0, %1;" : "=f"(y) : "f"(x)); return y;
}
// pack two fp32 (log2-domain) into half2, exponentiate both with ONE MUFU op
__device__ __forceinline__ unsigned ex2h2(float a, float b) {
    __half2 h = __floats2half2_rn(a, b);
    unsigned hu = *(unsigned*)&h, r;
    asm("ex2.approx.f16x2 %0, %1;" : "=r"(r) : "r"(hu));
    return r;
}
__device__ __forceinline__ unsigned s2u(const void* p) {
    return (unsigned)__cvta_generic_to_shared(p);
}
__device__ __forceinline__ void cpa16(unsigned d, const void* s) {
    asm volatile("cp.async.cg.shared.global [%0], [%1], 16;" :: "r"(d), "l"(s));
}
__device__ __forceinline__ void cpcommit() { asm volatile("cp.async.commit_group;"); }
template<int N> __device__ __forceinline__ void cpwait() {
    asm volatile("cp.async.wait_group %0;" :: "n"(N));
}
__device__ __forceinline__ void ldsm4(unsigned& r0, unsigned& r1, unsigned& r2, unsigned& r3, unsigned a) {
    asm volatile("ldmatrix.sync.aligned.m8n8.x4.shared.b16 {%0,%1,%2,%3}, [%4];"
                 : "=r"(r0), "=r"(r1), "=r"(r2), "=r"(r3) : "r"(a));
}
__device__ __forceinline__ void ldsm4t(unsigned& r0, unsigned& r1, unsigned& r2, unsigned& r3, unsigned a) {
    asm volatile("ldmatrix.sync.aligned.m8n8.x4.trans.shared.b16 {%0,%1,%2,%3}, [%4];"
                 : "=r"(r0), "=r"(r1), "=r"(r2), "=r"(r3) : "r"(a));
}
__device__ __forceinline__ void mma16816(float* c, const unsigned* a, unsigned b0, unsigned b1) {
    asm volatile(
        "mma.sync.aligned.m16n8k16.row.col.f32.f16.f16.f32 "
        "{%0,%1,%2,%3}, {%4,%5,%6,%7}, {%8,%9}, {%0,%1,%2,%3};\n"
        : "+f"(c[0]), "+f"(c[1]), "+f"(c[2]), "+f"(c[3])
        : "r"(a[0]), "r"(a[1]), "r"(a[2]), "r"(a[3]), "r"(b0), "r"(b1));
}

// ---------------- kernel 0: fused prep (x convert + both weight transposes) ----------------
// grid.x sections: [0, 4096) x_convert | [4096, 4096+3072) wqkv | [+1024) wout
#define XCONV_BLOCKS (MTOT*DIMM/(256*8))      // 4096
#define WQKV_BLOCKS  ((3*DIMM/32)*(DIMM/32))  // 3072
#define WOUT_BLOCKS  ((DIMM/32)*(DIMM/32))    // 1024
__global__ void prep_kernel(const float* __restrict__ X,
                            const float* __restrict__ Wqkv,
                            const float* __restrict__ Wout) {
    int blk = blockIdx.x;
    if (blk < XCONV_BLOCKS) {
        int tid = threadIdx.x;                 // 256 threads, 8 floats each
        int i = blk * 256 + tid;
        const float4* Xv = (const float4*)X;
        float4 a = Xv[2*i], b = Xv[2*i + 1];
        __half2 h0 = __floats2half2_rn(a.x, a.y);
        __half2 h1 = __floats2half2_rn(a.z, a.w);
        __half2 h2 = __floats2half2_rn(b.x, b.y);
        __half2 h3 = __floats2half2_rn(b.z, b.w);
        uint4 u;
        u.x = *(unsigned*)&h0; u.y = *(unsigned*)&h1;
        u.z = *(unsigned*)&h2; u.w = *(unsigned*)&h3;
        *(uint4*)&g_xh[(size_t)i * 8] = u;
        return;
    }
    __shared__ float tile[32][33];
    const float* in;
    __half* out;
    int nb, kb, Nc;
    if (blk < XCONV_BLOCKS + WQKV_BLOCKS) {
        int b2 = blk - XCONV_BLOCKS;
        in = Wqkv; out = g_wqkvT; Nc = 3*DIMM;
        nb = (b2 % (3*DIMM/32)) * 32; kb = (b2 / (3*DIMM/32)) * 32;
    } else {
        int b2 = blk - XCONV_BLOCKS - WQKV_BLOCKS;
        in = Wout; out = g_woutT; Nc = DIMM;
        nb = (b2 % (DIMM/32)) * 32; kb = (b2 / (DIMM/32)) * 32;
    }
    int tx = threadIdx.x & 31, ty = threadIdx.x >> 5;  // 32x8
    #pragma unroll
    for (int i = 0; i < 32; i += 8)
        tile[ty + i][tx] = in[(size_t)(kb + ty + i) * Nc + nb + tx];
    __syncthreads();
    #pragma unroll
    for (int i = 0; i < 32; i += 8)
        out[(size_t)(nb + ty + i) * DIMM + kb + tx] = __float2half_rn(tile[tx][ty + i]);
}

// ---------------- dense GEMM core: CTA 128x128, warp 64x32, K-chunk 32, 4 stages (R12 winner) ----------------
#define ST_A_H   (128 * PAD2)
#define ST_H     (2 * ST_A_H)                 // 10240 halves = 20480 B
#define KITERS   (DIMM / 32)                  // 32
#define GEMM2_SMEM (4 * ST_H * (int)sizeof(__half))   // 81920 B

__device__ __forceinline__ void g2_stage(__half* sbuf, const __half* Ag, const __half* Bg,
                                         int kt, int tid) {
    __half* sA = sbuf;
    __half* sB = sbuf + ST_A_H;
    int r0 = tid >> 2, c = tid & 3;
    #pragma unroll
    for (int i = 0; i < 2; i++) {
        int r = r0 + i * 64;
        cpa16(s2u(&sA[r * PAD2 + c * 8]), &Ag[(size_t)r * DIMM + kt * 32 + c * 8]);
        cpa16(s2u(&sB[r * PAD2 + c * 8]), &Bg[(size_t)r * DIMM + kt * 32 + c * 8]);
    }
}

__device__ __forceinline__ void g2_compute(const __half* sbuf, float acc[4][4][4],
                                           int lane, int wm, int wn) {
    const __half* sA = sbuf;
    const __half* sB = sbuf + ST_A_H;
    int r8 = lane & 7;
    int b3 = (lane >> 3) & 1, b4 = (lane >> 4) & 1;
    #pragma unroll
    for (int kk = 0; kk < 2; kk++) {
        unsigned a[4][4], b[4][2];
        #pragma unroll
        for (int mt = 0; mt < 4; mt++) {
            unsigned ad = s2u(&sA[(wm*64 + mt*16 + b3*8 + r8) * PAD2 + kk*16 + b4*8]);
            ldsm4(a[mt][0], a[mt][1], a[mt][2], a[mt][3], ad);
        }
        #pragma unroll
        for (int jp = 0; jp < 2; jp++) {
            unsigned bd = s2u(&sB[(wn*32 + jp*16 + b4*8 + r8) * PAD2 + kk*16 + b3*8]);
            unsigned u0, u1, u2, u3;
            ldsm4(u0, u1, u2, u3, bd);
            b[2*jp][0] = u0;   b[2*jp][1] = u1;
            b[2*jp+1][0] = u2; b[2*jp+1][1] = u3;
        }
        #pragma unroll
        for (int mt = 0; mt < 4; mt++)
            #pragma unroll
            for (int nt = 0; nt < 4; nt++)
                mma16816(acc[mt][nt], a[mt], b[nt][0], b[nt][1]);
    }
}

__device__ __forceinline__ void g2_mainloop(__half* smem, const __half* Ag, const __half* Bg,
                                            float acc[4][4][4], int tid, int lane,
                                            int wm, int wn) {
    #pragma unroll
    for (int s = 0; s < 3; s++) {
        g2_stage(smem + s * ST_H, Ag, Bg, s, tid);
        cpcommit();
    }
    for (int kt = 0; kt < KITERS; kt++) {
        cpwait<2>();
        __syncthreads();
        g2_compute(smem + (kt & 3) * ST_H, acc, lane, wm, wn);
        if (kt + 3 < KITERS)
            g2_stage(smem + ((kt + 3) & 3) * ST_H, Ag, Bg, kt + 3, tid);
        cpcommit();   // exactly one commit per iter: wait<2> bound stays exact
    }
}

// ---------------- kernel 1: QKV GEMM (128x128 tiles) ----------------
__global__ __launch_bounds__(256, 2) void qkv_gemm() {
    extern __shared__ __half smem_[];
    int bn = blockIdx.x, bm = blockIdx.y;
    int tid = threadIdx.x, lane = tid & 31, warp = tid >> 5;
    int wm = warp >> 2, wn = warp & 3;
    int g = lane >> 2, t = lane & 3;
    const __half* Ag = g_xh + (size_t)bm * 128 * DIMM;
    const __half* Bg = g_wqkvT + (size_t)bn * 128 * DIMM;

    float acc[4][4][4];
    #pragma unroll
    for (int i = 0; i < 4; i++)
        #pragma unroll
        for (int j = 0; j < 4; j++)
            #pragma unroll
            for (int k = 0; k < 4; k++) acc[i][j][k] = 0.f;

    g2_mainloop(smem_, Ag, Bg, acc, tid, lane, wm, wn);

    int sec = bn >> 3;
    __half* dst = sec == 0 ? g_q : (sec == 1 ? g_k : g_v);
    float scale = (sec == 0) ? 0.125f : 1.0f;
    #pragma unroll
    for (int mt = 0; mt < 4; mt++) {
        int r = bm*128 + wm*64 + mt*16 + g;
        int bb = r >> 11, nq = r & (SEQ - 1);
        #pragma unroll
        for (int nt = 0; nt < 4; nt++) {
            int cc = (bn & 7)*128 + wn*32 + nt*8 + 2*t;
            int h = cc >> 6, d = cc & 63;
            int o = ((bb*HEADS + h)*SEQ + nq)*DHEAD + d;
            *(__half2*)&dst[o] = __floats2half2_rn(acc[mt][nt][0]*scale, acc[mt][nt][1]*scale);
            *(__half2*)&dst[o + 8*DHEAD] = __floats2half2_rn(acc[mt][nt][2]*scale, acc[mt][nt][3]*scale);
        }
    }
}

// ---------------- kernel 3: out proj (128x128 tiles) ----------------
__global__ __launch_bounds__(256, 2) void out_gemm(const float* __restrict__ bias,
                                                   float* __restrict__ out) {
    extern __shared__ __half smem_[];
    int bn = blockIdx.x, bm = blockIdx.y;
    int tid = threadIdx.x, lane = tid & 31, warp = tid >> 5;
    int wm = warp >> 2, wn = warp & 3;
    int g = lane >> 2, t = lane & 3;
    const __half* Ag = g_ao + (size_t)bm * 128 * DIMM;
    const __half* Bg = g_woutT + (size_t)bn * 128 * DIMM;

    float acc[4][4][4];
    #pragma unroll
    for (int i = 0; i < 4; i++)
        #pragma unroll
        for (int j = 0; j < 4; j++)
            #pragma unroll
            for (int k = 0; k < 4; k++) acc[i][j][k] = 0.f;

    g2_mainloop(smem_, Ag, Bg, acc, tid, lane, wm, wn);

    #pragma unroll
    for (int mt = 0; mt < 4; mt++) {
        int r = bm*128 + wm*64 + mt*16 + g;
        #pragma unroll
        for (int nt = 0; nt < 4; nt++) {
            int c = bn*128 + wn*32 + nt*8 + 2*t;
            float2 bv = *(const float2*)&bias[c];
            float2 r0; r0.x = acc[mt][nt][0] + bv.x; r0.y = acc[mt][nt][1] + bv.y;
            float2 r1; r1.x = acc[mt][nt][2] + bv.x; r1.y = acc[mt][nt][3] + bv.y;
            *(float2*)&out[(size_t)r*DIMM + c] = r0;
            *(float2*)&out[(size_t)(r + 8)*DIMM + c] = r1;
        }
    }
}

// ---------------- kernel 2: flash attention, 4-deep KV ring, f16x2 softmax (R12 winner) ----------------
#define KV_H (64 * PAD)                       // halves per K (or V) tile
#define ATTN_SMEM ((128 * PAD + 8 * KV_H) * (int)sizeof(__half))
#define KVTILES (SEQ / 64)                    // 32

__device__ __forceinline__ void attn_stage_kv(__half* sK, __half* sV,
                                              const __half* Kg, const __half* Vg,
                                              int kv, int tid) {
    const __half* Kn = Kg + (size_t)kv * 64 * DHEAD;
    const __half* Vn = Vg + (size_t)kv * 64 * DHEAD;
    int r0 = tid >> 3, c = tid & 7;
    #pragma unroll
    for (int i = 0; i < 2; i++) {
        int r = r0 + i * 32;
        cpa16(s2u(&sK[r * PAD + c * 8]), &Kn[r * DHEAD + c * 8]);
        cpa16(s2u(&sV[r * PAD + c * 8]), &Vn[r * DHEAD + c * 8]);
    }
}

__global__ __launch_bounds__(256, 2) void attn_kernel() {
    extern __shared__ __half smem_[];
    __half* sQ  = smem_;                       // 128*PAD
    __half* sKr = smem_ + 128 * PAD;           // ring: 4 x KV_H
    __half* sVr = sKr + 4 * KV_H;              // ring: 4 x KV_H
    int rt = blockIdx.x, pair = blockIdx.y;
    int tid = threadIdx.x, lane = tid & 31, warp = tid >> 5;
    int g = lane >> 2, t = lane & 3;
    int r8 = lane & 7;
    int b3 = (lane >> 3) & 1, b4 = (lane >> 4) & 1;
    const __half* Qg = g_q + (size_t)pair * SEQ * DHEAD + (size_t)rt * 128 * DHEAD;
    const __half* Kg = g_k + (size_t)pair * SEQ * DHEAD;
    const __half* Vg = g_v + (size_t)pair * SEQ * DHEAD;

    // group 1: Q
    {
        int r0 = tid >> 3, c = tid & 7;
        #pragma unroll
        for (int i = 0; i < 4; i++) {
            int r = r0 + i * 32;
            cpa16(s2u(&sQ[r * PAD + c * 8]), &Qg[r * DHEAD + c * 8]);
        }
    }
    cpcommit();
    // groups 2..4: kv tiles 0..2
    attn_stage_kv(sKr + 0 * KV_H, sVr + 0 * KV_H, Kg, Vg, 0, tid); cpcommit();
    attn_stage_kv(sKr + 1 * KV_H, sVr + 1 * KV_H, Kg, Vg, 1, tid); cpcommit();
    attn_stage_kv(sKr + 2 * KV_H, sVr + 2 * KV_H, Kg, Vg, 2, tid); cpcommit();

    cpwait<3>();   // Q landed
    __syncthreads();
    unsigned qa[4][4];
    #pragma unroll
    for (int kk = 0; kk < 4; kk++) {
        unsigned ad = s2u(&sQ[(warp*16 + b3*8 + r8) * PAD + kk*16 + b4*8]);
        ldsm4(qa[kk][0], qa[kk][1], qa[kk][2], qa[kk][3], ad);
    }

    float m0 = -1e30f, m1 = -1e30f, l0 = 0.f, l1 = 0.f;
    float o[8][4];
    #pragma unroll
    for (int nd = 0; nd < 8; nd++)
        #pragma unroll
        for (int i = 0; i < 4; i++) o[nd][i] = 0.f;

    for (int kv = 0; kv < KVTILES; kv++) {
        // commits before this iter = 4 + kv; wait<2> -> completed >= kv+2 -> tile kv landed
        cpwait<2>();
        __syncthreads();
        // stage tile kv+3 into ring slot (kv+3)&3 = (kv-1)&3 (freed by the sync above)
        if (kv + 3 < KVTILES)
            attn_stage_kv(sKr + ((kv + 3) & 3) * KV_H, sVr + ((kv + 3) & 3) * KV_H,
                          Kg, Vg, kv + 3, tid);
        cpcommit();   // exactly one commit per iter
        const __half* cK = sKr + (kv & 3) * KV_H;
        const __half* cV = sVr + (kv & 3) * KV_H;

        float s[8][4];
        #pragma unroll
        for (int jn = 0; jn < 8; jn++)
            #pragma unroll
            for (int i = 0; i < 4; i++) s[jn][i] = 0.f;
        #pragma unroll
        for (int kk = 0; kk < 4; kk++)
            #pragma unroll
            for (int jp = 0; jp < 4; jp++) {
                unsigned bd = s2u(&cK[(jp*16 + b4*8 + r8) * PAD + kk*16 + b3*8]);
                unsigned u0, u1, u2, u3;
                ldsm4(u0, u1, u2, u3, bd);
                mma16816(s[2*jp],   qa[kk], u0, u1);
                mma16816(s[2*jp+1], qa[kk], u2, u3);
            }
        // online softmax (rows g = sum0, g+8 = sum1)
        float rmax0 = -1e30f, rmax1 = -1e30f;
        #pragma unroll
        for (int jn = 0; jn < 8; jn++) {
            rmax0 = fmaxf(rmax0, fmaxf(s[jn][0], s[jn][1]));
            rmax1 = fmaxf(rmax1, fmaxf(s[jn][2], s[jn][3]));
        }
        rmax0 = fmaxf(rmax0, __shfl_xor_sync(0xffffffffu, rmax0, 1));
        rmax0 = fmaxf(rmax0, __shfl_xor_sync(0xffffffffu, rmax0, 2));
        rmax1 = fmaxf(rmax1, __shfl_xor_sync(0xffffffffu, rmax1, 1));
        rmax1 = fmaxf(rmax1, __shfl_xor_sync(0xffffffffu, rmax1, 2));
        float mn0 = fmaxf(m0, rmax0), mn1 = fmaxf(m1, rmax1);
        float al0 = ex2f_((m0 - mn0) * LOG2E);
        float al1 = ex2f_((m1 - mn1) * LOG2E);
        float c0 = mn0 * LOG2E, c1 = mn1 * LOG2E;

        // P directly in fp16 A-fragment layout via f16x2 exp; sums from same fp16 P
        unsigned pa[4][4];
        float sum0 = 0.f, sum1 = 0.f;
        #pragma unroll
        for (int kk = 0; kk < 4; kk++) {
            pa[kk][0] = ex2h2(s[2*kk][0]  *LOG2E - c0, s[2*kk][1]  *LOG2E - c0);
            pa[kk][1] = ex2h2(s[2*kk][2]  *LOG2E - c1, s[2*kk][3]  *LOG2E - c1);
            pa[kk][2] = ex2h2(s[2*kk+1][0]*LOG2E - c0, s[2*kk+1][1]*LOG2E - c0);
            pa[kk][3] = ex2h2(s[2*kk+1][2]*LOG2E - c1, s[2*kk+1][3]*LOG2E - c1);
            __half2 e0 = __hadd2(*(__half2*)&pa[kk][0], *(__half2*)&pa[kk][2]);
            __half2 e1 = __hadd2(*(__half2*)&pa[kk][1], *(__half2*)&pa[kk][3]);
            float2 f0 = __half22float2(e0);
            float2 f1 = __half22float2(e1);
            sum0 += f0.x + f0.y;
            sum1 += f1.x + f1.y;
        }
        sum0 += __shfl_xor_sync(0xffffffffu, sum0, 1);
        sum0 += __shfl_xor_sync(0xffffffffu, sum0, 2);
        sum1 += __shfl_xor_sync(0xffffffffu, sum1, 1);
        sum1 += __shfl_xor_sync(0xffffffffu, sum1, 2);
        l0 = l0 * al0 + sum0;  l1 = l1 * al1 + sum1;
        m0 = mn0;  m1 = mn1;
        #pragma unroll
        for (int nd = 0; nd < 8; nd++) {
            o[nd][0] *= al0; o[nd][1] *= al0; o[nd][2] *= al1; o[nd][3] *= al1;
        }
        #pragma unroll
        for (int kk = 0; kk < 4; kk++)
            #pragma unroll
            for (int np = 0; np < 4; np++) {
                unsigned vd = s2u(&cV[(kk*16 + b3*8 + r8) * PAD + np*16 + b4*8]);
                unsigned u0, u1, u2, u3;
                ldsm4t(u0, u1, u2, u3, vd);
                mma16816(o[2*np],   pa[kk], u0, u1);
                mma16816(o[2*np+1], pa[kk], u2, u3);
            }
    }
    float inv0 = 1.0f / l0, inv1 = 1.0f / l1;
    int bb = pair >> 4, h = pair & 15;
    int r = rt*128 + warp*16 + g;
    size_t base0 = ((size_t)bb*SEQ + r)*DIMM + h*64;
    #pragma unroll
    for (int nd = 0; nd < 8; nd++) {
        int d = nd*8 + 2*t;
        *(__half2*)&g_ao[base0 + d] = __floats2half2_rn(o[nd][0]*inv0, o[nd][1]*inv0);
        *(__half2*)&g_ao[base0 + (size_t)8*DIMM + d] = __floats2half2_rn(o[nd][2]*inv1, o[nd][3]*inv1);
    }
}

// ---------------- launch ----------------
extern "C" void kernel_launch(void* const* d_in, const int* in_sizes, int n_in,
                              void* d_out, int out_size) {
    const float* x     = (const float*)d_in[0];
    const float* w_qkv = (const float*)d_in[1];
    const float* w_out = (const float*)d_in[2];
    const float* b_out = (const float*)d_in[3];
    float* out = (float*)d_out;

    cudaFuncSetAttribute(qkv_gemm, cudaFuncAttributeMaxDynamicSharedMemorySize, GEMM2_SMEM);
    cudaFuncSetAttribute(out_gemm, cudaFuncAttributeMaxDynamicSharedMemorySize, GEMM2_SMEM);
    cudaFuncSetAttribute(attn_kernel, cudaFuncAttributeMaxDynamicSharedMemorySize, ATTN_SMEM);

    prep_kernel<<<XCONV_BLOCKS + WQKV_BLOCKS + WOUT_BLOCKS, 256>>>(x, w_qkv, w_out);
    qkv_gemm<<<dim3(3*DIMM/128, MTOT/128), 256, GEMM2_SMEM>>>();
    attn_kernel<<<dim3(SEQ/128, BATCH*HEADS), 256, ATTN_SMEM>>>();
    out_gemm<<<dim3(DIMM/128, MTOT/128), 256, GEMM2_SMEM>>>(b_out, out);
}